// round 1
// baseline (speedup 1.0000x reference)
#include <cuda_runtime.h>
#include <math.h>

#define Bsz 512
#define Tt  1024
#define Dd  64
#define Hh  64
#define NB  4
#define Rr  4
#define MHh 32

__device__ __forceinline__ float fsigmoid(float v){
    return 1.0f / (1.0f + __expf(-v));
}
// Saturation-safe fast tanh: exp argument always <= 0, never overflows.
__device__ __forceinline__ float ftanh(float v){
    float t = __expf(-2.0f * fabsf(v));
    float r = (1.0f - t) / (1.0f + t);
    return copysignf(r, v);
}

// ---------------------------------------------------------------------------
// LSTM: 128 blocks x 256 threads. Block handles NB=4 batch rows.
// Thread j owns gate-unit j (gate = j>>6, unit = j&63); its W_ih / W_hh rows
// live in registers for the whole T loop. h/x are broadcast from shared.
// ---------------------------------------------------------------------------
__global__ __launch_bounds__(256, 1)
void lstm_kernel(const float* __restrict__ x,
                 const float* __restrict__ h_init,
                 const float* __restrict__ c_init,
                 const float* __restrict__ W_ih,
                 const float* __restrict__ W_hh,
                 const float* __restrict__ b_ih,
                 const float* __restrict__ b_hh,
                 float* __restrict__ y)
{
    const int j    = threadIdx.x;   // 0..255 gate-unit
    const int u    = j & 63;
    const int gate = j >> 6;        // 0:i 1:f 2:g 3:o
    const int bb   = gate;          // also used as this thread's batch for x loads
    const int b0   = blockIdx.x * NB;

    __shared__ __align__(16) float hs[NB][Hh];
    __shared__ __align__(16) float xs[NB][Hh];
    __shared__ float gact[NB][256];

    // Weights into registers (float4 loads, fully unrolled so they stay in regs)
    float wih[Dd], whh[Hh];
#pragma unroll
    for (int k = 0; k < Dd; k += 4){
        float4 a  = *(const float4*)&W_ih[j * Dd + k];
        wih[k]=a.x; wih[k+1]=a.y; wih[k+2]=a.z; wih[k+3]=a.w;
        float4 c4 = *(const float4*)&W_hh[j * Hh + k];
        whh[k]=c4.x; whh[k+1]=c4.y; whh[k+2]=c4.z; whh[k+3]=c4.w;
    }
    const float bj = b_ih[j] + b_hh[j];

    float creg[NB];
    if (j < Hh){
        float h0 = h_init[j];
        float c0 = c_init[j];
#pragma unroll
        for (int b = 0; b < NB; b++){ hs[b][j] = h0; creg[b] = c0; }
    }

    const float* xptr = x + ((size_t)(b0 + bb)) * Tt * Dd + u;
    float xn = __ldg(xptr);           // prefetch t=0
    __syncthreads();

    for (int t = 0; t < Tt; t++){
        xs[bb][u] = xn;
        __syncthreads();
        if (t + 1 < Tt) xn = __ldg(xptr + (size_t)(t + 1) * Dd);  // hide DRAM latency

        float acc[NB];
#pragma unroll
        for (int b = 0; b < NB; b++) acc[b] = bj;

        // input projection: acc += W_ih[j,:] . x_t
#pragma unroll
        for (int k = 0; k < Dd; k += 4){
#pragma unroll
            for (int b = 0; b < NB; b++){
                float4 v = *(const float4*)&xs[b][k];
                acc[b] = fmaf(wih[k  ], v.x, acc[b]);
                acc[b] = fmaf(wih[k+1], v.y, acc[b]);
                acc[b] = fmaf(wih[k+2], v.z, acc[b]);
                acc[b] = fmaf(wih[k+3], v.w, acc[b]);
            }
        }
        // recurrence: acc += W_hh[j,:] . h_{t-1}
#pragma unroll
        for (int k = 0; k < Hh; k += 4){
#pragma unroll
            for (int b = 0; b < NB; b++){
                float4 v = *(const float4*)&hs[b][k];
                acc[b] = fmaf(whh[k  ], v.x, acc[b]);
                acc[b] = fmaf(whh[k+1], v.y, acc[b]);
                acc[b] = fmaf(whh[k+2], v.z, acc[b]);
                acc[b] = fmaf(whh[k+3], v.w, acc[b]);
            }
        }

        // gate activation (i,f,o: sigmoid; g: tanh)
#pragma unroll
        for (int b = 0; b < NB; b++){
            float v = acc[b];
            gact[b][j] = (gate == 2) ? ftanh(v) : fsigmoid(v);
        }
        __syncthreads();

        if (j < Hh){
#pragma unroll
            for (int b = 0; b < NB; b++){
                float ig = gact[b][j];
                float fg = gact[b][ 64 + j];
                float gg = gact[b][128 + j];
                float og = gact[b][192 + j];
                float cn = fmaf(fg, creg[b], ig * gg);
                creg[b] = cn;
                float hn = og * ftanh(cn);
                hs[b][j] = hn;
                y[((size_t)(b0 + b)) * Tt * Hh + (size_t)t * Hh + j] = hn;
            }
        }
        __syncthreads();
    }
}

// ---------------------------------------------------------------------------
// Heads: 4096 blocks x 128 threads; one (b,t) column per thread, all R heads.
// Weights in shared (float4 broadcast reads). y staged transposed (stride-129
// rows -> conflict-free column reads). h1/h2 live in per-thread shared columns
// so the m/n loops stay rolled (small SASS, no register spills).
// ---------------------------------------------------------------------------
__global__ __launch_bounds__(128)
void heads_kernel(const float* __restrict__ y,
                  const float* __restrict__ W1, const float* __restrict__ b1,
                  const float* __restrict__ W2, const float* __restrict__ b2,
                  const float* __restrict__ W3, const float* __restrict__ b3,
                  float* __restrict__ outs)
{
    extern __shared__ float sm[];
    float* W1s = sm;                   // 4*32*64 = 8192
    float* W2s = W1s + 8192;           // 4*32*32 = 4096
    float* W3s = W2s + 4096;           // 128
    float* b1s = W3s + 128;            // 128
    float* b2s = b1s + 128;            // 128
    float* b3s = b2s + 128;            // 4 (+pad)
    float* ys  = b3s + 8;              // 64*129 = 8256, reused below
    float* h1s = ys;                   // 32*128 = 4096 (after yv extracted)
    float* h2s = ys + 4096;            // 32*128 = 4096

    const int tid  = threadIdx.x;
    const size_t bt0 = (size_t)blockIdx.x * 128;
    const size_t BT  = (size_t)Bsz * Tt;

    for (int i = tid; i < Rr*MHh*Hh;  i += 128) W1s[i] = W1[i];
    for (int i = tid; i < Rr*MHh*MHh; i += 128) W2s[i] = W2[i];
    if (tid < Rr*MHh){ W3s[tid] = W3[tid]; b1s[tid] = b1[tid]; b2s[tid] = b2[tid]; }
    if (tid < Rr) b3s[tid] = b3[tid];

    // stage y tile transposed: ys[h*129 + btl]  (coalesced gmem read)
    for (int e = tid; e < 128 * Hh; e += 128){
        int btl = e >> 6;
        int h   = e & 63;
        ys[h * 129 + btl] = y[bt0 * Hh + e];
    }
    __syncthreads();

    float yv[Hh];
#pragma unroll
    for (int h = 0; h < Hh; h++) yv[h] = ys[h * 129 + tid];  // conflict-free
    __syncthreads();   // ys region reused as h1s/h2s after this

    for (int r = 0; r < Rr; r++){
        for (int m = 0; m < MHh; m++){
            float acc = b1s[r*MHh + m];
            const float4* w = (const float4*)(W1s + (r*MHh + m) * Hh);
#pragma unroll
            for (int q = 0; q < 16; q++){
                float4 ww = w[q];
                acc = fmaf(ww.x, yv[4*q+0], acc);
                acc = fmaf(ww.y, yv[4*q+1], acc);
                acc = fmaf(ww.z, yv[4*q+2], acc);
                acc = fmaf(ww.w, yv[4*q+3], acc);
            }
            h1s[m * 128 + tid] = fmaxf(acc, 0.0f);   // same-thread column, no sync needed
        }
        for (int n = 0; n < MHh; n++){
            float acc = b2s[r*MHh + n];
            const float4* w = (const float4*)(W2s + (r*MHh + n) * MHh);
#pragma unroll
            for (int q = 0; q < 8; q++){
                float4 ww = w[q];
                acc = fmaf(ww.x, h1s[(4*q+0)*128 + tid], acc);
                acc = fmaf(ww.y, h1s[(4*q+1)*128 + tid], acc);
                acc = fmaf(ww.z, h1s[(4*q+2)*128 + tid], acc);
                acc = fmaf(ww.w, h1s[(4*q+3)*128 + tid], acc);
            }
            h2s[n * 128 + tid] = fmaxf(acc, 0.0f);
        }
        float o = b3s[r];
        const float4* w3 = (const float4*)(W3s + r * MHh);
#pragma unroll
        for (int q = 0; q < 8; q++){
            float4 ww = w3[q];
            o = fmaf(ww.x, h2s[(4*q+0)*128 + tid], o);
            o = fmaf(ww.y, h2s[(4*q+1)*128 + tid], o);
            o = fmaf(ww.z, h2s[(4*q+2)*128 + tid], o);
            o = fmaf(ww.w, h2s[(4*q+3)*128 + tid], o);
        }
        outs[(size_t)r * BT + bt0 + tid] = o;
    }
}

extern "C" void kernel_launch(void* const* d_in, const int* in_sizes, int n_in,
                              void* d_out, int out_size)
{
    const float* x      = (const float*)d_in[0];
    const float* h_init = (const float*)d_in[1];
    const float* c_init = (const float*)d_in[2];
    const float* W_ih   = (const float*)d_in[3];
    const float* W_hh   = (const float*)d_in[4];
    const float* b_ih   = (const float*)d_in[5];
    const float* b_hh   = (const float*)d_in[6];
    const float* W1     = (const float*)d_in[7];
    const float* b1     = (const float*)d_in[8];
    const float* W2     = (const float*)d_in[9];
    const float* b2     = (const float*)d_in[10];
    const float* W3     = (const float*)d_in[11];
    const float* b3     = (const float*)d_in[12];

    float* y    = (float*)d_out;                       // (B, T, H)
    float* outs = y + (size_t)Bsz * Tt * Hh;           // (R, B, T)

    lstm_kernel<<<Bsz / NB, 256>>>(x, h_init, c_init, W_ih, W_hh, b_ih, b_hh, y);

    const size_t shmem = 20936 * sizeof(float);        // ~83.7 KB dynamic
    cudaFuncSetAttribute(heads_kernel,
                         cudaFuncAttributeMaxDynamicSharedMemorySize, (int)shmem);
    heads_kernel<<<(Bsz * Tt) / 128, 128, shmem>>>(y, W1, b1, W2, b2, W3, b3, outs);
}

// round 3
// speedup vs baseline: 1.2243x; 1.2243x over previous
#include <cuda_runtime.h>
#include <math.h>

#define Bsz 512
#define Tt  1024
#define Dd  64
#define Hh  64
#define NB  4
#define Rr  4
#define MHh 32

typedef unsigned long long ull;

__device__ __forceinline__ void fma2(ull &d, ull a, ull b){
    asm("fma.rn.f32x2 %0, %1, %2, %0;" : "+l"(d) : "l"(a), "l"(b));
}
__device__ __forceinline__ ull pack2(float lo, float hi){
    ull r; asm("mov.b64 %0, {%1, %2};" : "=l"(r) : "f"(lo), "f"(hi)); return r;
}
__device__ __forceinline__ float2 unpack2(ull v){
    float2 r; asm("mov.b64 {%0, %1}, %2;" : "=f"(r.x), "=f"(r.y) : "l"(v)); return r;
}

__device__ __forceinline__ float fsigmoid(float v){
    return 1.0f / (1.0f + __expf(-v));
}
// Saturation-safe fast tanh: exp argument always <= 0, never overflows.
__device__ __forceinline__ float ftanh(float v){
    float t = __expf(-2.0f * fabsf(v));
    float r = (1.0f - t) / (1.0f + t);
    return copysignf(r, v);
}

// ---------------------------------------------------------------------------
// LSTM: 128 blocks x 256 threads, NB=4 batch rows per block.
// Thread j owns gate-row j (weights in registers, packed f32x2 pairs along k)
// AND the h/c state of (batch = j>>6, unit = j&63) so the per-step tail is
// spread over all 256 threads. All gate math uses packed fma.rn.f32x2.
// ---------------------------------------------------------------------------
__global__ __launch_bounds__(256, 1)
void lstm_kernel(const float* __restrict__ x,
                 const float* __restrict__ h_init,
                 const float* __restrict__ c_init,
                 const float* __restrict__ W_ih,
                 const float* __restrict__ W_hh,
                 const float* __restrict__ b_ih,
                 const float* __restrict__ b_hh,
                 float* __restrict__ y)
{
    const int j    = threadIdx.x;    // 0..255: gate-unit row
    const int u    = j & 63;
    const int gate = j >> 6;         // 0:i 1:f 2:g 3:o ; doubles as owned batch
    const int b0   = blockIdx.x * NB;

    __shared__ __align__(16) float hs[NB][Hh];
    __shared__ __align__(16) float xs[NB][Hh];
    __shared__ float gact[NB][256];

    // Weights as packed f32x2 pairs (k-contiguous => zero-cost packing)
    ull wih[Dd/2], whh[Hh/2];
#pragma unroll
    for (int k = 0; k < Dd/2; k += 2){
        ulonglong2 a = *(const ulonglong2*)&W_ih[j * Dd + 2*k];
        wih[k] = a.x; wih[k+1] = a.y;
        ulonglong2 c = *(const ulonglong2*)&W_hh[j * Hh + 2*k];
        whh[k] = c.x; whh[k+1] = c.y;
    }
    const float bj = b_ih[j] + b_hh[j];

    // per-thread recurrent state for (batch=gate, unit=u)
    float creg = c_init[u];
    hs[gate][u] = h_init[u];

    const float* xptr = x + ((size_t)(b0 + gate)) * Tt * Dd + u;
    float xn = __ldg(xptr);          // prefetch t=0
    __syncthreads();

    for (int t = 0; t < Tt; t++){
        xs[gate][u] = xn;
        __syncthreads();
        if (t + 1 < Tt) xn = __ldg(xptr + (size_t)(t + 1) * Dd);

        // two independent f32x2 accumulator chains per batch (x-part, h-part)
        ull accx[NB], acch[NB];
#pragma unroll
        for (int b = 0; b < NB; b++){ accx[b] = pack2(bj, 0.0f); acch[b] = 0ULL; }

#pragma unroll
        for (int k = 0; k < Dd; k += 4){
#pragma unroll
            for (int b = 0; b < NB; b++){
                ulonglong2 v = *(const ulonglong2*)&xs[b][k];   // broadcast LDS.128
                fma2(accx[b], wih[k/2    ], v.x);
                fma2(accx[b], wih[k/2 + 1], v.y);
            }
        }
#pragma unroll
        for (int k = 0; k < Hh; k += 4){
#pragma unroll
            for (int b = 0; b < NB; b++){
                ulonglong2 v = *(const ulonglong2*)&hs[b][k];
                fma2(acch[b], whh[k/2    ], v.x);
                fma2(acch[b], whh[k/2 + 1], v.y);
            }
        }

#pragma unroll
        for (int b = 0; b < NB; b++){
            float2 px = unpack2(accx[b]);
            float2 ph = unpack2(acch[b]);
            float g = (px.x + ph.x) + (px.y + ph.y);
            gact[b][j] = (gate == 2) ? ftanh(g) : fsigmoid(g);
        }
        __syncthreads();

        // h/c update, all 256 threads: (batch=gate, unit=u)
        {
            float ig = gact[gate][      u];
            float fg = gact[gate][ 64 + u];
            float gg = gact[gate][128 + u];
            float og = gact[gate][192 + u];
            float cn = fmaf(fg, creg, ig * gg);
            creg = cn;
            float hn = og * ftanh(cn);
            hs[gate][u] = hn;
            y[((size_t)(b0 + gate)) * Tt * Hh + (size_t)t * Hh + u] = hn;
        }
        // top-of-loop __syncthreads covers hs-write -> next gate-read
    }
}

// ---------------------------------------------------------------------------
// Heads: 4096 blocks x 128 threads, 2 blocks/SM. One bt column per thread.
// y, h1, h2 all live in registers as packed f32x2 pairs; weights broadcast
// from shared via ulonglong2. No intermediate shared spills.
// Each ulonglong2 covers 4 floats: W1 rows (64) -> q<16, W2/W3 rows (32) -> q<8.
// ---------------------------------------------------------------------------
__global__ __launch_bounds__(128, 2)
void heads_kernel(const float* __restrict__ y,
                  const float* __restrict__ W1, const float* __restrict__ b1,
                  const float* __restrict__ W2, const float* __restrict__ b2,
                  const float* __restrict__ W3, const float* __restrict__ b3,
                  float* __restrict__ outs)
{
    extern __shared__ float sm[];
    float* W1s = sm;                 // 8192
    float* W2s = W1s + 8192;         // 4096
    float* W3s = W2s + 4096;         // 128
    float* b1s = W3s + 128;          // 128
    float* b2s = b1s + 128;          // 128
    float* b3s = b2s + 128;          // 8 (padded)
    float* ys  = b3s + 8;            // 64 * 133 = 8512 (pad 133: conflict-free)

    const int tid    = threadIdx.x;
    const size_t bt0 = (size_t)blockIdx.x * 128;
    const size_t BT  = (size_t)Bsz * Tt;

    for (int i = tid; i < Rr*MHh*Hh;  i += 128) W1s[i] = W1[i];
    for (int i = tid; i < Rr*MHh*MHh; i += 128) W2s[i] = W2[i];
    if (tid < Rr*MHh){ W3s[tid] = W3[tid]; b1s[tid] = b1[tid]; b2s[tid] = b2[tid]; }
    if (tid < Rr) b3s[tid] = b3[tid];

    // stage y tile transposed (coalesced gmem read, conflict-free smem write)
    for (int i = tid; i < 128 * Hh; i += 128){
        int btl = i >> 6;
        int h   = i & 63;
        ys[h * 133 + btl] = y[bt0 * Hh + i];
    }
    __syncthreads();

    // y column into registers as f32x2 pairs along h (32 pairs = 64 floats)
    ull yv[Hh/2];
#pragma unroll
    for (int k = 0; k < Hh/2; k++)
        yv[k] = pack2(ys[(2*k) * 133 + tid], ys[(2*k+1) * 133 + tid]);

    for (int r = 0; r < Rr; r++){
        ull h1p[MHh/2];
#pragma unroll
        for (int m = 0; m < MHh; m += 2){
            float hm[2];
#pragma unroll
            for (int mm = 0; mm < 2; mm++){
                const ulonglong2* w = (const ulonglong2*)(W1s + (r*MHh + m + mm) * Hh);
                ull a0 = 0ULL, a1 = 0ULL;
#pragma unroll
                for (int q = 0; q < 16; q++){       // 16 * 4 floats = 64
                    ulonglong2 ww = w[q];           // broadcast LDS.128
                    fma2(a0, ww.x, yv[2*q    ]);
                    fma2(a1, ww.y, yv[2*q + 1]);
                }
                float2 p0 = unpack2(a0), p1 = unpack2(a1);
                hm[mm] = fmaxf(b1s[r*MHh + m + mm] + ((p0.x + p1.x) + (p0.y + p1.y)), 0.0f);
            }
            h1p[m/2] = pack2(hm[0], hm[1]);
        }

        ull h2p[MHh/2];
#pragma unroll
        for (int n = 0; n < MHh; n += 2){
            float hv[2];
#pragma unroll
            for (int nn = 0; nn < 2; nn++){
                const ulonglong2* w = (const ulonglong2*)(W2s + (r*MHh + n + nn) * MHh);
                ull a0 = 0ULL, a1 = 0ULL;
#pragma unroll
                for (int q = 0; q < 8; q++){        // 8 * 4 floats = 32
                    ulonglong2 ww = w[q];
                    fma2(a0, ww.x, h1p[2*q    ]);
                    fma2(a1, ww.y, h1p[2*q + 1]);
                }
                float2 p0 = unpack2(a0), p1 = unpack2(a1);
                hv[nn] = fmaxf(b2s[r*MHh + n + nn] + ((p0.x + p1.x) + (p0.y + p1.y)), 0.0f);
            }
            h2p[n/2] = pack2(hv[0], hv[1]);
        }

        const ulonglong2* w3 = (const ulonglong2*)(W3s + r * MHh);
        ull a0 = 0ULL, a1 = 0ULL;
#pragma unroll
        for (int q = 0; q < 8; q++){                // 8 * 4 floats = 32
            ulonglong2 ww = w3[q];
            fma2(a0, ww.x, h2p[2*q    ]);
            fma2(a1, ww.y, h2p[2*q + 1]);
        }
        float2 p0 = unpack2(a0), p1 = unpack2(a1);
        outs[(size_t)r * BT + bt0 + tid] = b3s[r] + ((p0.x + p1.x) + (p0.y + p1.y));
    }
}

extern "C" void kernel_launch(void* const* d_in, const int* in_sizes, int n_in,
                              void* d_out, int out_size)
{
    const float* x      = (const float*)d_in[0];
    const float* h_init = (const float*)d_in[1];
    const float* c_init = (const float*)d_in[2];
    const float* W_ih   = (const float*)d_in[3];
    const float* W_hh   = (const float*)d_in[4];
    const float* b_ih   = (const float*)d_in[5];
    const float* b_hh   = (const float*)d_in[6];
    const float* W1     = (const float*)d_in[7];
    const float* b1     = (const float*)d_in[8];
    const float* W2     = (const float*)d_in[9];
    const float* b2     = (const float*)d_in[10];
    const float* W3     = (const float*)d_in[11];
    const float* b3     = (const float*)d_in[12];

    float* y    = (float*)d_out;                     // (B, T, H)
    float* outs = y + (size_t)Bsz * Tt * Hh;         // (R, B, T)

    lstm_kernel<<<Bsz / NB, 256>>>(x, h_init, c_init, W_ih, W_hh, b_ih, b_hh, y);

    const size_t shmem = 21192 * sizeof(float);      // 84768 B
    cudaFuncSetAttribute(heads_kernel,
                         cudaFuncAttributeMaxDynamicSharedMemorySize, (int)shmem);
    heads_kernel<<<(Bsz * Tt) / 128, 128, shmem>>>(y, W1, b1, W2, b2, W3, b3, outs);
}